// round 5
// baseline (speedup 1.0000x reference)
#include <cuda_runtime.h>
#include <mma.h>

using namespace nvcuda;

// Problem constants
#define IN_DIM 512
#define BATCH  1024
#define NN1    25
#define NN2    10
#define D1     128
#define D2     128
#define NCLS   41
#define ROWS1  (BATCH * NN1)        // 25600

// Scratch (device globals; no cudaMalloc allowed)
__device__ float g_h2  [ROWS1 * 2 * D2];   // 26.2 MB (raw GEMM out, pre-bias/relu)
__device__ float g_agg1[BATCH * 2 * D2];   // 1 MB

// ---------------------------------------------------------------------------
// Kernel B (fused): h2_raw = A @ W  (no bias/relu; folded into agg1)
//   half 0: A = features[ids1[r]],          W = W2s -> h2[:, 0:128]
//   half 1: A = agg2 computed ON THE FLY,   W = W2n -> h2[:, 128:256]
//     agg2[g, d] = mean_k concat(features[ids2[g*10..]])[d*10+k]
//     -> per k-tile kt, column dc needs 10 consecutive floats at flat offset
//        (kt*32+dc)*10, spanning <=2 source rows. Gather+reduce direct to sA.
// wmma tf32 16x16x8, fp32 accumulate. BM=64, BN=128, BK=32, 256 threads.
// ---------------------------------------------------------------------------
#define BM  64
#define BK  32
#define LDA 36
#define LDB 132

__global__ void gemm2_kernel(const float* __restrict__ features,
                             const int* __restrict__ ids1,
                             const int* __restrict__ ids2,
                             const float* __restrict__ W2s,
                             const float* __restrict__ W2n) {
    __shared__ float sA[BM * LDA];       // 9.2 KB
    __shared__ float sB[BK * LDB];       // 16.9 KB
    __shared__ int   sIdx[BM * NN2];     // 2.5 KB (half0 uses first 64)

    const int half = blockIdx.y;
    const int tid  = threadIdx.x;
    const int row0 = blockIdx.x * BM;
    const float* __restrict__ W = half ? W2n : W2s;

    if (half == 0) {
        if (tid < BM) sIdx[tid] = ids1[row0 + tid];
    } else {
        for (int i = tid; i < BM * NN2; i += 256)
            sIdx[i] = ids2[row0 * NN2 + i];
    }
    __syncthreads();

    wmma::fragment<wmma::accumulator, 16, 16, 8, float> acc[2][2];
#pragma unroll
    for (int i = 0; i < 2; i++)
#pragma unroll
        for (int j = 0; j < 2; j++) wmma::fill_fragment(acc[i][j], 0.0f);

    const int warp = tid >> 5;
    const int m0 = (warp >> 2) * 32;   // 0 or 32
    const int n0 = (warp & 3) * 32;    // 0,32,64,96

    for (int kt = 0; kt < IN_DIM / BK; kt++) {
        if (half == 0) {
            // A tile (64 x 32) gathered from features rows: 512 float4
            for (int i = tid; i < BM * BK / 4; i += 256) {
                const int r  = i >> 3;
                const int c4 = i & 7;
                *reinterpret_cast<float4*>(&sA[r * LDA + c4 * 4]) =
                    *reinterpret_cast<const float4*>(
                        features + (size_t)sIdx[r] * IN_DIM + kt * BK + c4 * 4);
            }
        } else {
            // A tile = agg2 slice computed on the fly. 2048 elems, 8/thread.
            // elem = tid + e*256 -> group-row i2 = elem>>5 (uniform per warp),
            // dc = lane -> warp reads a contiguous 1280B span per group.
#pragma unroll
            for (int e = 0; e < 8; e++) {
                const int elem = tid + e * 256;
                const int i2 = elem >> 5;
                const int dc = elem & 31;
                const int p0 = kt * 320 + dc * 10;   // flat offset of 10-run
                const int r0 = p0 >> 9;
                const int c0 = p0 & 511;
                const float* s1 = features + (size_t)sIdx[i2 * NN2 + r0] * IN_DIM;
                float s = 0.f;
                if (c0 <= IN_DIM - 10) {
#pragma unroll
                    for (int k = 0; k < 10; k++) s += s1[c0 + k];
                } else {
                    const int n1 = IN_DIM - c0;
                    for (int k = 0; k < n1; k++) s += s1[c0 + k];
                    const float* s2 =
                        features + (size_t)sIdx[i2 * NN2 + r0 + 1] * IN_DIM;
                    for (int k = n1; k < 10; k++) s += s2[k - n1];
                }
                sA[i2 * LDA + dc] = s * (1.0f / NN2);
            }
        }
        // B tile (32 x 128): 1024 float4 (weights L2-resident)
        for (int i = tid; i < BK * 128 / 4; i += 256) {
            const int r  = i >> 5;
            const int c4 = i & 31;
            *reinterpret_cast<float4*>(&sB[r * LDB + c4 * 4]) =
                *reinterpret_cast<const float4*>(
                    W + (size_t)(kt * BK + r) * 128 + c4 * 4);
        }
        __syncthreads();

#pragma unroll
        for (int kk = 0; kk < BK; kk += 8) {
            wmma::fragment<wmma::matrix_a, 16, 16, 8, wmma::precision::tf32,
                           wmma::row_major> af[2];
            wmma::fragment<wmma::matrix_b, 16, 16, 8, wmma::precision::tf32,
                           wmma::row_major> bf[2];
#pragma unroll
            for (int i = 0; i < 2; i++) {
                wmma::load_matrix_sync(af[i], &sA[(m0 + i * 16) * LDA + kk], LDA);
#pragma unroll
                for (int t = 0; t < af[i].num_elements; t++)
                    af[i].x[t] = wmma::__float_to_tf32(af[i].x[t]);
            }
#pragma unroll
            for (int j = 0; j < 2; j++) {
                wmma::load_matrix_sync(bf[j], &sB[kk * LDB + n0 + j * 16], LDB);
#pragma unroll
                for (int t = 0; t < bf[j].num_elements; t++)
                    bf[j].x[t] = wmma::__float_to_tf32(bf[j].x[t]);
            }
#pragma unroll
            for (int i = 0; i < 2; i++)
#pragma unroll
                for (int j = 0; j < 2; j++)
                    wmma::mma_sync(acc[i][j], af[i], bf[j], acc[i][j]);
        }
        __syncthreads();
    }

#pragma unroll
    for (int i = 0; i < 2; i++)
#pragma unroll
        for (int j = 0; j < 2; j++)
            wmma::store_matrix_sync(
                g_h2 + (size_t)(row0 + m0 + i * 16) * (2 * D2) + half * D2 + n0 + j * 16,
                acc[i][j], 2 * D2, wmma::mem_row_major);
}

// ---------------------------------------------------------------------------
// Kernel C: agg1[b,d] = mean_k relu(h2_raw + bias)[flat b*6400 + d*25 + k]
// bias[c] = c<128 ? b2s[c] : b2n[c-128]. One block per batch element, 256 thr.
// ---------------------------------------------------------------------------
__global__ void agg1_kernel(const float* __restrict__ b2s,
                            const float* __restrict__ b2n) {
    __shared__ float sbuf[NN1 * 2 * D2];   // 6400 floats
    __shared__ float sbias[2 * D2];
    const int g   = blockIdx.x;
    const int tid = threadIdx.x;   // 256

    sbias[tid] = (tid < D2) ? b2s[tid] : b2n[tid - D2];
    __syncthreads();

    const float* src = g_h2 + (size_t)g * NN1 * 2 * D2;
    for (int i = tid; i < NN1 * 2 * D2; i += 256) {
        const int c = i & 255;
        sbuf[i] = fmaxf(src[i] + sbias[c], 0.0f);
    }
    __syncthreads();

    const float* p = sbuf + tid * NN1;
    float s = 0.f;
#pragma unroll
    for (int k = 0; k < NN1; k++) s += p[k];
    g_agg1[g * 2 * D2 + tid] = s * (1.0f / NN1);
}

// ---------------------------------------------------------------------------
// Kernel D: 4 batch rows per block (weight traffic /4), 256 threads.
//   h1 = [f0@W1s+b1s, agg1@W1n+b1n]; out = h1@Wfc + bfc
// ---------------------------------------------------------------------------
#define HRPB 4
__global__ void head_kernel(const float* __restrict__ features,
                            const int* __restrict__ ids0,
                            const float* __restrict__ W1s,
                            const float* __restrict__ b1s,
                            const float* __restrict__ W1n,
                            const float* __restrict__ b1n,
                            const float* __restrict__ Wfc,
                            const float* __restrict__ bfc,
                            float* __restrict__ out) {
    __shared__ float sF0[HRPB * IN_DIM];    // 8 KB
    __shared__ float sA1[HRPB * 2 * D2];    // 4 KB
    __shared__ float sH1[HRPB * 2 * D1];    // 4 KB
    const int row0 = blockIdx.x * HRPB;
    const int tid  = threadIdx.x;           // 256

    // Gather 4 f0 rows (512 float4) + 4 agg1 rows (256 float4)
    for (int i = tid; i < HRPB * IN_DIM / 4; i += 256) {
        const int r  = i >> 7;
        const int c4 = i & 127;
        const int id = ids0[row0 + r];
        reinterpret_cast<float4*>(sF0)[i] =
            *(reinterpret_cast<const float4*>(features + (size_t)id * IN_DIM) + c4);
    }
    if (tid < HRPB * 2 * D2 / 4)
        reinterpret_cast<float4*>(sA1)[tid] =
            reinterpret_cast<const float4*>(g_agg1 + (size_t)row0 * 2 * D2)[tid];
    __syncthreads();

    if (tid < D1) {
        // self path: out col tid, K=512, 4 rows, 2 accs/row
        float a0[HRPB], a1[HRPB];
#pragma unroll
        for (int r = 0; r < HRPB; r++) { a0[r] = 0.f; a1[r] = 0.f; }
        for (int k = 0; k < IN_DIM; k += 4) {
            const float w0 = W1s[(k + 0) * D1 + tid];
            const float w1 = W1s[(k + 1) * D1 + tid];
            const float w2 = W1s[(k + 2) * D1 + tid];
            const float w3 = W1s[(k + 3) * D1 + tid];
#pragma unroll
            for (int r = 0; r < HRPB; r++) {
                const float4 f = *reinterpret_cast<const float4*>(&sF0[r * IN_DIM + k]);
                a0[r] = fmaf(f.x, w0, a0[r]);
                a1[r] = fmaf(f.y, w1, a1[r]);
                a0[r] = fmaf(f.z, w2, a0[r]);
                a1[r] = fmaf(f.w, w3, a1[r]);
            }
        }
        const float bb = b1s[tid];
#pragma unroll
        for (int r = 0; r < HRPB; r++) sH1[r * 2 * D1 + tid] = a0[r] + a1[r] + bb;
    } else {
        // neighbor path: out col t, K=256, 4 rows
        const int t = tid - D1;
        float a0[HRPB], a1[HRPB];
#pragma unroll
        for (int r = 0; r < HRPB; r++) { a0[r] = 0.f; a1[r] = 0.f; }
        for (int k = 0; k < 2 * D2; k += 4) {
            const float w0 = W1n[(k + 0) * D1 + t];
            const float w1 = W1n[(k + 1) * D1 + t];
            const float w2 = W1n[(k + 2) * D1 + t];
            const float w3 = W1n[(k + 3) * D1 + t];
#pragma unroll
            for (int r = 0; r < HRPB; r++) {
                const float4 f = *reinterpret_cast<const float4*>(&sA1[r * 2 * D2 + k]);
                a0[r] = fmaf(f.x, w0, a0[r]);
                a1[r] = fmaf(f.y, w1, a1[r]);
                a0[r] = fmaf(f.z, w2, a0[r]);
                a1[r] = fmaf(f.w, w3, a1[r]);
            }
        }
        const float bb = b1n[t];
#pragma unroll
        for (int r = 0; r < HRPB; r++) sH1[r * 2 * D1 + D1 + t] = a0[r] + a1[r] + bb;
    }
    __syncthreads();

    // Classifier: (row,class) pairs over 8 warps; lanes split K, shfl reduce
    const int warp = tid >> 5;
    const int lane = tid & 31;
    for (int pc = warp; pc < HRPB * NCLS; pc += 8) {
        const int r = pc / NCLS;
        const int c = pc % NCLS;
        float s = 0.f;
#pragma unroll
        for (int k = lane; k < 2 * D1; k += 32)
            s = fmaf(sH1[r * 2 * D1 + k], Wfc[k * NCLS + c], s);
#pragma unroll
        for (int off = 16; off > 0; off >>= 1)
            s += __shfl_xor_sync(0xFFFFFFFFu, s, off);
        if (lane == 0) out[(row0 + r) * NCLS + c] = s + bfc[c];
    }
}

// ---------------------------------------------------------------------------
extern "C" void kernel_launch(void* const* d_in, const int* in_sizes, int n_in,
                              void* d_out, int out_size) {
    const float* features = (const float*)d_in[0];
    const int*   ids0     = (const int*)  d_in[1];
    const int*   ids1     = (const int*)  d_in[2];
    const int*   ids2     = (const int*)  d_in[3];
    const float* W2s      = (const float*)d_in[4];
    const float* b2s      = (const float*)d_in[5];
    const float* W2n      = (const float*)d_in[6];
    const float* b2n      = (const float*)d_in[7];
    const float* W1s      = (const float*)d_in[8];
    const float* b1s      = (const float*)d_in[9];
    const float* W1n      = (const float*)d_in[10];
    const float* b1n      = (const float*)d_in[11];
    const float* Wfc      = (const float*)d_in[12];
    const float* bfc      = (const float*)d_in[13];
    float* out = (float*)d_out;

    gemm2_kernel<<<dim3(ROWS1 / BM, 2), 256>>>(features, ids1, ids2, W2s, W2n);
    agg1_kernel<<<BATCH, 256>>>(b2s, b2n);
    head_kernel<<<BATCH / HRPB, 256>>>(features, ids0, W1s, b1s, W1n, b1n,
                                       Wfc, bfc, out);
}

// round 6
// speedup vs baseline: 2.4212x; 2.4212x over previous
#include <cuda_runtime.h>
#include <mma.h>

using namespace nvcuda;

// Problem constants
#define IN_DIM 512
#define BATCH  1024
#define NN1    25
#define NN2    10
#define D1     128
#define D2     128
#define NCLS   41
#define ROWS1  (BATCH * NN1)        // 25600

// Scratch (device globals; no cudaMalloc allowed)
__device__ float g_agg2[ROWS1 * IN_DIM];   // 52.4 MB
__device__ float g_h2  [ROWS1 * 2 * D2];   // 26.2 MB (raw GEMM out, pre-bias/relu)
__device__ float g_agg1[BATCH * 2 * D2];   // 1 MB

// ---------------------------------------------------------------------------
// Kernel A: agg2[i,d] = mean_k flat[i*5120 + d*10 + k], flat = gathered f2 rows
// One block per group of 10 rows. 128 threads. High-MLP coalesced gather.
// ---------------------------------------------------------------------------
__global__ void agg2_kernel(const float* __restrict__ features,
                            const int* __restrict__ ids2) {
    __shared__ float sbuf[NN2 * IN_DIM];   // 5120 floats
    __shared__ int   sIds[NN2];
    const int g   = blockIdx.x;
    const int tid = threadIdx.x;

    if (tid < NN2) sIds[tid] = ids2[g * NN2 + tid];
    __syncthreads();

    float4* s4 = reinterpret_cast<float4*>(sbuf);
#pragma unroll
    for (int j = 0; j < 10; j++) {
        const int i = tid + j * 128;            // 1280 float4 total
        const int r  = i >> 7;
        const int c4 = i & 127;
        s4[i] = *(reinterpret_cast<const float4*>(
                      features + (size_t)sIds[r] * IN_DIM) + c4);
    }
    __syncthreads();

    float* outRow = g_agg2 + (size_t)g * IN_DIM;
#pragma unroll
    for (int j = 0; j < 4; j++) {
        const int d = tid + j * 128;
        const float* p = sbuf + d * NN2;
        float s = 0.f;
#pragma unroll
        for (int k = 0; k < NN2; k++) s += p[k];
        outRow[d] = s * (1.0f / NN2);
    }
}

// ---------------------------------------------------------------------------
// Kernel B: h2_raw = A @ W  (no bias/relu; folded into agg1)
//   half 0: A = features[ids1[r]],  W = W2s  -> h2[:, 0:128]
//   half 1: A = g_agg2[r],          W = W2n  -> h2[:, 128:256]
// wmma tf32 16x16x8, fp32 accumulate. BM=64, BN=128, BK=32, 256 threads.
// tf32 rounding applied at the SMEM STORE (no per-fragment conversion loops
// -> fewer live regs; __launch_bounds__ forces 2 blocks/SM).
// ---------------------------------------------------------------------------
#define BM  64
#define BK  32
#define LDA 36
#define LDB 132

__device__ __forceinline__ float4 to_tf32x4(float4 v) {
    v.x = wmma::__float_to_tf32(v.x);
    v.y = wmma::__float_to_tf32(v.y);
    v.z = wmma::__float_to_tf32(v.z);
    v.w = wmma::__float_to_tf32(v.w);
    return v;
}

__global__ __launch_bounds__(256, 2)
void gemm2_kernel(const float* __restrict__ features,
                  const int* __restrict__ ids1,
                  const float* __restrict__ W2s,
                  const float* __restrict__ W2n) {
    __shared__ float sA[BM * LDA];   // 9.2 KB
    __shared__ float sB[BK * LDB];   // 16.9 KB
    __shared__ int   sIds[BM];

    const int half = blockIdx.y;
    const int tid  = threadIdx.x;
    const int row0 = blockIdx.x * BM;
    const float* __restrict__ W = half ? W2n : W2s;

    if (half == 0 && tid < BM) sIds[tid] = ids1[row0 + tid];
    __syncthreads();

    wmma::fragment<wmma::accumulator, 16, 16, 8, float> acc[2][2];
#pragma unroll
    for (int i = 0; i < 2; i++)
#pragma unroll
        for (int j = 0; j < 2; j++) wmma::fill_fragment(acc[i][j], 0.0f);

    const int warp = tid >> 5;
    const int m0 = (warp >> 2) * 32;   // 0 or 32
    const int n0 = (warp & 3) * 32;    // 0,32,64,96

    for (int kt = 0; kt < IN_DIM / BK; kt++) {
        // A tile (64 x 32): 512 float4, rounded to tf32 on store
#pragma unroll
        for (int u = 0; u < 2; u++) {
            const int i  = tid + u * 256;
            const int r  = i >> 3;
            const int c4 = i & 7;
            const float* src = (half == 0)
                ? features + (size_t)sIds[r] * IN_DIM + kt * BK + c4 * 4
                : g_agg2  + (size_t)(row0 + r) * IN_DIM + kt * BK + c4 * 4;
            *reinterpret_cast<float4*>(&sA[r * LDA + c4 * 4]) =
                to_tf32x4(*reinterpret_cast<const float4*>(src));
        }
        // B tile (32 x 128): 1024 float4 (weights L2-resident)
#pragma unroll
        for (int u = 0; u < 4; u++) {
            const int i  = tid + u * 256;
            const int r  = i >> 5;
            const int c4 = i & 31;
            *reinterpret_cast<float4*>(&sB[r * LDB + c4 * 4]) =
                to_tf32x4(*reinterpret_cast<const float4*>(
                    W + (size_t)(kt * BK + r) * 128 + c4 * 4));
        }
        __syncthreads();

#pragma unroll
        for (int kk = 0; kk < BK; kk += 8) {
            wmma::fragment<wmma::matrix_a, 16, 16, 8, wmma::precision::tf32,
                           wmma::row_major> af[2];
            wmma::fragment<wmma::matrix_b, 16, 16, 8, wmma::precision::tf32,
                           wmma::row_major> bf[2];
#pragma unroll
            for (int i = 0; i < 2; i++)
                wmma::load_matrix_sync(af[i], &sA[(m0 + i * 16) * LDA + kk], LDA);
#pragma unroll
            for (int j = 0; j < 2; j++)
                wmma::load_matrix_sync(bf[j], &sB[kk * LDB + n0 + j * 16], LDB);
#pragma unroll
            for (int i = 0; i < 2; i++)
#pragma unroll
                for (int j = 0; j < 2; j++)
                    wmma::mma_sync(acc[i][j], af[i], bf[j], acc[i][j]);
        }
        __syncthreads();
    }

#pragma unroll
    for (int i = 0; i < 2; i++)
#pragma unroll
        for (int j = 0; j < 2; j++)
            wmma::store_matrix_sync(
                g_h2 + (size_t)(row0 + m0 + i * 16) * (2 * D2) + half * D2 + n0 + j * 16,
                acc[i][j], 2 * D2, wmma::mem_row_major);
}

// ---------------------------------------------------------------------------
// Kernel C: agg1[b,d] = mean_k relu(h2_raw + bias)[flat b*6400 + d*25 + k]
// bias[c] = c<128 ? b2s[c] : b2n[c-128]. One block per batch element, 256 thr.
// ---------------------------------------------------------------------------
__global__ void agg1_kernel(const float* __restrict__ b2s,
                            const float* __restrict__ b2n) {
    __shared__ float sbuf[NN1 * 2 * D2];   // 6400 floats
    __shared__ float sbias[2 * D2];
    const int g   = blockIdx.x;
    const int tid = threadIdx.x;   // 256

    sbias[tid] = (tid < D2) ? b2s[tid] : b2n[tid - D2];
    __syncthreads();

    const float* src = g_h2 + (size_t)g * NN1 * 2 * D2;
    for (int i = tid; i < NN1 * 2 * D2; i += 256) {
        const int c = i & 255;
        sbuf[i] = fmaxf(src[i] + sbias[c], 0.0f);
    }
    __syncthreads();

    const float* p = sbuf + tid * NN1;
    float s = 0.f;
#pragma unroll
    for (int k = 0; k < NN1; k++) s += p[k];
    g_agg1[g * 2 * D2 + tid] = s * (1.0f / NN1);
}

// ---------------------------------------------------------------------------
// Kernel D: 4 batch rows per block (weight traffic /4), 256 threads.
//   h1 = [f0@W1s+b1s, agg1@W1n+b1n]; out = h1@Wfc + bfc
// ---------------------------------------------------------------------------
#define HRPB 4
__global__ void head_kernel(const float* __restrict__ features,
                            const int* __restrict__ ids0,
                            const float* __restrict__ W1s,
                            const float* __restrict__ b1s,
                            const float* __restrict__ W1n,
                            const float* __restrict__ b1n,
                            const float* __restrict__ Wfc,
                            const float* __restrict__ bfc,
                            float* __restrict__ out) {
    __shared__ float sF0[HRPB * IN_DIM];    // 8 KB
    __shared__ float sA1[HRPB * 2 * D2];    // 4 KB
    __shared__ float sH1[HRPB * 2 * D1];    // 4 KB
    const int row0 = blockIdx.x * HRPB;
    const int tid  = threadIdx.x;           // 256

    for (int i = tid; i < HRPB * IN_DIM / 4; i += 256) {
        const int r  = i >> 7;
        const int c4 = i & 127;
        const int id = ids0[row0 + r];
        reinterpret_cast<float4*>(sF0)[i] =
            *(reinterpret_cast<const float4*>(features + (size_t)id * IN_DIM) + c4);
    }
    if (tid < HRPB * 2 * D2 / 4)
        reinterpret_cast<float4*>(sA1)[tid] =
            reinterpret_cast<const float4*>(g_agg1 + (size_t)row0 * 2 * D2)[tid];
    __syncthreads();

    if (tid < D1) {
        float a0[HRPB], a1[HRPB];
#pragma unroll
        for (int r = 0; r < HRPB; r++) { a0[r] = 0.f; a1[r] = 0.f; }
        for (int k = 0; k < IN_DIM; k += 4) {
            const float w0 = W1s[(k + 0) * D1 + tid];
            const float w1 = W1s[(k + 1) * D1 + tid];
            const float w2 = W1s[(k + 2) * D1 + tid];
            const float w3 = W1s[(k + 3) * D1 + tid];
#pragma unroll
            for (int r = 0; r < HRPB; r++) {
                const float4 f = *reinterpret_cast<const float4*>(&sF0[r * IN_DIM + k]);
                a0[r] = fmaf(f.x, w0, a0[r]);
                a1[r] = fmaf(f.y, w1, a1[r]);
                a0[r] = fmaf(f.z, w2, a0[r]);
                a1[r] = fmaf(f.w, w3, a1[r]);
            }
        }
        const float bb = b1s[tid];
#pragma unroll
        for (int r = 0; r < HRPB; r++) sH1[r * 2 * D1 + tid] = a0[r] + a1[r] + bb;
    } else {
        const int t = tid - D1;
        float a0[HRPB], a1[HRPB];
#pragma unroll
        for (int r = 0; r < HRPB; r++) { a0[r] = 0.f; a1[r] = 0.f; }
        for (int k = 0; k < 2 * D2; k += 4) {
            const float w0 = W1n[(k + 0) * D1 + t];
            const float w1 = W1n[(k + 1) * D1 + t];
            const float w2 = W1n[(k + 2) * D1 + t];
            const float w3 = W1n[(k + 3) * D1 + t];
#pragma unroll
            for (int r = 0; r < HRPB; r++) {
                const float4 f = *reinterpret_cast<const float4*>(&sA1[r * 2 * D2 + k]);
                a0[r] = fmaf(f.x, w0, a0[r]);
                a1[r] = fmaf(f.y, w1, a1[r]);
                a0[r] = fmaf(f.z, w2, a0[r]);
                a1[r] = fmaf(f.w, w3, a1[r]);
            }
        }
        const float bb = b1n[t];
#pragma unroll
        for (int r = 0; r < HRPB; r++) sH1[r * 2 * D1 + D1 + t] = a0[r] + a1[r] + bb;
    }
    __syncthreads();

    const int warp = tid >> 5;
    const int lane = tid & 31;
    for (int pc = warp; pc < HRPB * NCLS; pc += 8) {
        const int r = pc / NCLS;
        const int c = pc % NCLS;
        float s = 0.f;
#pragma unroll
        for (int k = lane; k < 2 * D1; k += 32)
            s = fmaf(sH1[r * 2 * D1 + k], Wfc[k * NCLS + c], s);
#pragma unroll
        for (int off = 16; off > 0; off >>= 1)
            s += __shfl_xor_sync(0xFFFFFFFFu, s, off);
        if (lane == 0) out[(row0 + r) * NCLS + c] = s + bfc[c];
    }
}

// ---------------------------------------------------------------------------
extern "C" void kernel_launch(void* const* d_in, const int* in_sizes, int n_in,
                              void* d_out, int out_size) {
    const float* features = (const float*)d_in[0];
    const int*   ids0     = (const int*)  d_in[1];
    const int*   ids1     = (const int*)  d_in[2];
    const int*   ids2     = (const int*)  d_in[3];
    const float* W2s      = (const float*)d_in[4];
    const float* b2s      = (const float*)d_in[5];
    const float* W2n      = (const float*)d_in[6];
    const float* b2n      = (const float*)d_in[7];
    const float* W1s      = (const float*)d_in[8];
    const float* b1s      = (const float*)d_in[9];
    const float* W1n      = (const float*)d_in[10];
    const float* b1n      = (const float*)d_in[11];
    const float* Wfc      = (const float*)d_in[12];
    const float* bfc      = (const float*)d_in[13];
    float* out = (float*)d_out;

    agg2_kernel<<<ROWS1, 128>>>(features, ids2);
    gemm2_kernel<<<dim3(ROWS1 / BM, 2), 256>>>(features, ids1, W2s, W2n);
    agg1_kernel<<<BATCH, 256>>>(b2s, b2n);
    head_kernel<<<BATCH / HRPB, 256>>>(features, ids0, W1s, b1s, W1n, b1n,
                                       Wfc, bfc, out);
}

// round 7
// speedup vs baseline: 2.6716x; 1.1034x over previous
#include <cuda_runtime.h>
#include <mma.h>

using namespace nvcuda;

// Problem constants
#define IN_DIM 512
#define BATCH  1024
#define NN1    25
#define NN2    10
#define D1     128
#define D2     128
#define NCLS   41
#define ROWS1  (BATCH * NN1)        // 25600

// Scratch (device globals; no cudaMalloc allowed)
__device__ float g_agg2[ROWS1 * IN_DIM];   // 52.4 MB
__device__ float g_h2  [ROWS1 * 2 * D2];   // 26.2 MB (raw GEMM out, pre-bias/relu)
__device__ float g_agg1[BATCH * 2 * D2];   // 1 MB

__device__ __forceinline__ void cp16(void* smem_dst, const void* gmem_src) {
    unsigned s = (unsigned)__cvta_generic_to_shared(smem_dst);
    asm volatile("cp.async.cg.shared.global [%0], [%1], 16;\n"
                 :: "r"(s), "l"(gmem_src));
}

// ---------------------------------------------------------------------------
// Kernel A: agg2[i,d] = mean_k flat[i*5120 + d*10 + k], flat = gathered f2 rows
// One block per group of 10 rows. 128 threads. High-MLP coalesced gather.
// ---------------------------------------------------------------------------
__global__ void agg2_kernel(const float* __restrict__ features,
                            const int* __restrict__ ids2) {
    __shared__ float sbuf[NN2 * IN_DIM];   // 5120 floats
    __shared__ int   sIds[NN2];
    const int g   = blockIdx.x;
    const int tid = threadIdx.x;

    if (tid < NN2) sIds[tid] = ids2[g * NN2 + tid];
    __syncthreads();

    float4* s4 = reinterpret_cast<float4*>(sbuf);
#pragma unroll
    for (int j = 0; j < 10; j++) {
        const int i = tid + j * 128;            // 1280 float4 total
        const int r  = i >> 7;
        const int c4 = i & 127;
        s4[i] = *(reinterpret_cast<const float4*>(
                      features + (size_t)sIds[r] * IN_DIM) + c4);
    }
    __syncthreads();

    float* outRow = g_agg2 + (size_t)g * IN_DIM;
#pragma unroll
    for (int j = 0; j < 4; j++) {
        const int d = tid + j * 128;
        const float* p = sbuf + d * NN2;
        float s = 0.f;
#pragma unroll
        for (int k = 0; k < NN2; k++) s += p[k];
        outRow[d] = s * (1.0f / NN2);
    }
}

// ---------------------------------------------------------------------------
// Kernel B: h2_raw = A @ W  (no bias/relu; folded into agg1)
//   blockIdx.y = half*2 + ntile (half: 0=self/W2s, 1=neigh/W2n; ntile: 64-col)
//   half 0: A = features[ids1[r]];  half 1: A = g_agg2[r]
// wmma tf32 16x16x8 fp32-acc. BM=64, BN=64, BK=32, 256 threads.
// cp.async double-buffered tiles; fp32 bits fed to HMMA.TF32 (HW truncates).
// ---------------------------------------------------------------------------
#define BM  64
#define BN  64
#define BK  32
#define LDA 36
#define LDB 68

__global__ __launch_bounds__(256, 3)
void gemm2_kernel(const float* __restrict__ features,
                  const int* __restrict__ ids1,
                  const float* __restrict__ W2s,
                  const float* __restrict__ W2n) {
    __shared__ float sA[2][BM * LDA];   // 2 x 9.0 KB
    __shared__ float sB[2][BK * LDB];   // 2 x 8.5 KB
    __shared__ int   sIds[BM];

    const int tid  = threadIdx.x;
    const int half = blockIdx.y >> 1;
    const int nt   = blockIdx.y & 1;
    const int row0 = blockIdx.x * BM;
    const float* __restrict__ W = half ? W2n : W2s;

    if (half == 0 && tid < BM) sIds[tid] = ids1[row0 + tid];
    __syncthreads();

    // tile loaders: one cp.async group per k-tile (A: 512 f4, B: 512 f4)
    auto loadTiles = [&](int kt, int buf) {
#pragma unroll
        for (int u = 0; u < 2; u++) {
            const int i  = tid + u * 256;
            const int r  = i >> 3;
            const int c4 = i & 7;
            const float* src = half
                ? g_agg2  + (size_t)(row0 + r) * IN_DIM + kt * BK + c4 * 4
                : features + (size_t)sIds[r] * IN_DIM + kt * BK + c4 * 4;
            cp16(&sA[buf][r * LDA + c4 * 4], src);
        }
#pragma unroll
        for (int u = 0; u < 2; u++) {
            const int i  = tid + u * 256;
            const int r  = i >> 4;
            const int c4 = i & 15;
            cp16(&sB[buf][r * LDB + c4 * 4],
                 W + (size_t)(kt * BK + r) * 128 + nt * BN + c4 * 4);
        }
        asm volatile("cp.async.commit_group;\n");
    };

    wmma::fragment<wmma::accumulator, 16, 16, 8, float> acc[2];
    wmma::fill_fragment(acc[0], 0.0f);
    wmma::fill_fragment(acc[1], 0.0f);

    const int warp = tid >> 5;
    const int m0 = (warp >> 1) * 16;   // 0,16,32,48
    const int n0 = (warp & 1) * 32;    // 0,32

    loadTiles(0, 0);

    for (int kt = 0; kt < IN_DIM / BK; kt++) {
        const int cur = kt & 1;
        if (kt < IN_DIM / BK - 1) {
            loadTiles(kt + 1, cur ^ 1);
            asm volatile("cp.async.wait_group 1;\n");
        } else {
            asm volatile("cp.async.wait_group 0;\n");
        }
        __syncthreads();

#pragma unroll
        for (int kk = 0; kk < BK; kk += 8) {
            wmma::fragment<wmma::matrix_a, 16, 16, 8, wmma::precision::tf32,
                           wmma::row_major> af;
            wmma::fragment<wmma::matrix_b, 16, 16, 8, wmma::precision::tf32,
                           wmma::row_major> bf[2];
            wmma::load_matrix_sync(af, &sA[cur][m0 * LDA + kk], LDA);
#pragma unroll
            for (int j = 0; j < 2; j++)
                wmma::load_matrix_sync(bf[j], &sB[cur][kk * LDB + n0 + j * 16], LDB);
            wmma::mma_sync(acc[0], af, bf[0], acc[0]);
            wmma::mma_sync(acc[1], af, bf[1], acc[1]);
        }
        __syncthreads();
    }

#pragma unroll
    for (int j = 0; j < 2; j++)
        wmma::store_matrix_sync(
            g_h2 + (size_t)(row0 + m0) * (2 * D2) + half * D2 + nt * BN + n0 + j * 16,
            acc[j], 2 * D2, wmma::mem_row_major);
}

// ---------------------------------------------------------------------------
// Kernel C: agg1[b,d] = mean_k relu(h2_raw + bias)[flat b*6400 + d*25 + k]
// bias[c] = c<128 ? b2s[c] : b2n[c-128]. One block per batch element, 256 thr.
// ---------------------------------------------------------------------------
__global__ void agg1_kernel(const float* __restrict__ b2s,
                            const float* __restrict__ b2n) {
    __shared__ float sbuf[NN1 * 2 * D2];   // 6400 floats
    __shared__ float sbias[2 * D2];
    const int g   = blockIdx.x;
    const int tid = threadIdx.x;   // 256

    sbias[tid] = (tid < D2) ? b2s[tid] : b2n[tid - D2];
    __syncthreads();

    const float4* src4 = reinterpret_cast<const float4*>(
        g_h2 + (size_t)g * NN1 * 2 * D2);
    float4* dst4 = reinterpret_cast<float4*>(sbuf);
    for (int i = tid; i < NN1 * 2 * D2 / 4; i += 256) {
        const int c4 = (i & 63) * 4;       // col within 256-wide row
        float4 v = src4[i];
        v.x = fmaxf(v.x + sbias[c4 + 0], 0.f);
        v.y = fmaxf(v.y + sbias[c4 + 1], 0.f);
        v.z = fmaxf(v.z + sbias[c4 + 2], 0.f);
        v.w = fmaxf(v.w + sbias[c4 + 3], 0.f);
        dst4[i] = v;
    }
    __syncthreads();

    const float* p = sbuf + tid * NN1;
    float s = 0.f;
#pragma unroll
    for (int k = 0; k < NN1; k++) s += p[k];
    g_agg1[g * 2 * D2 + tid] = s * (1.0f / NN1);
}

// ---------------------------------------------------------------------------
// Kernel D: 2 rows/block, 512 threads (one (row,col) pair per thread).
//   h1 = [f0@W1s+b1s, agg1@W1n+b1n]; out = h1@Wfc + bfc
// grid=512 -> ~3 blocks/SM; weight traffic halved vs 1-row/block.
// ---------------------------------------------------------------------------
#define HRPB 2
__global__ __launch_bounds__(512)
void head_kernel(const float* __restrict__ features,
                 const int* __restrict__ ids0,
                 const float* __restrict__ W1s,
                 const float* __restrict__ b1s,
                 const float* __restrict__ W1n,
                 const float* __restrict__ b1n,
                 const float* __restrict__ Wfc,
                 const float* __restrict__ bfc,
                 float* __restrict__ out) {
    __shared__ float sF0[HRPB * IN_DIM];    // 4 KB
    __shared__ float sA1[HRPB * 2 * D2];    // 2 KB
    __shared__ float sH1[HRPB * 2 * D1];    // 2 KB
    const int row0 = blockIdx.x * HRPB;
    const int tid  = threadIdx.x;           // 512

    if (tid < HRPB * IN_DIM / 4) {          // 256 float4
        const int r  = tid >> 7;
        const int c4 = tid & 127;
        const int id = ids0[row0 + r];
        reinterpret_cast<float4*>(sF0)[tid] =
            *(reinterpret_cast<const float4*>(features + (size_t)id * IN_DIM) + c4);
    } else if (tid < HRPB * IN_DIM / 4 + HRPB * 2 * D2 / 4) {
        const int j = tid - HRPB * IN_DIM / 4;   // 128 float4
        reinterpret_cast<float4*>(sA1)[j] =
            reinterpret_cast<const float4*>(g_agg1 + (size_t)row0 * 2 * D2)[j];
    }
    __syncthreads();

    const int r = tid >> 8;        // 0..1
    const int c = tid & 255;       // 0..255
    if (c < D1) {
        // self path: K=512
        float a0 = 0.f, a1 = 0.f, a2 = 0.f, a3 = 0.f;
        const float* f = sF0 + r * IN_DIM;
#pragma unroll 8
        for (int k = 0; k < IN_DIM; k += 4) {
            const float4 v = *reinterpret_cast<const float4*>(&f[k]);
            a0 = fmaf(v.x, W1s[(k + 0) * D1 + c], a0);
            a1 = fmaf(v.y, W1s[(k + 1) * D1 + c], a1);
            a2 = fmaf(v.z, W1s[(k + 2) * D1 + c], a2);
            a3 = fmaf(v.w, W1s[(k + 3) * D1 + c], a3);
        }
        sH1[r * 2 * D1 + c] = (a0 + a1) + (a2 + a3) + b1s[c];
    } else {
        // neighbor path: K=256
        const int t = c - D1;
        float a0 = 0.f, a1 = 0.f, a2 = 0.f, a3 = 0.f;
        const float* f = sA1 + r * 2 * D2;
#pragma unroll 8
        for (int k = 0; k < 2 * D2; k += 4) {
            const float4 v = *reinterpret_cast<const float4*>(&f[k]);
            a0 = fmaf(v.x, W1n[(k + 0) * D1 + t], a0);
            a1 = fmaf(v.y, W1n[(k + 1) * D1 + t], a1);
            a2 = fmaf(v.z, W1n[(k + 2) * D1 + t], a2);
            a3 = fmaf(v.w, W1n[(k + 3) * D1 + t], a3);
        }
        sH1[r * 2 * D1 + D1 + t] = (a0 + a1) + (a2 + a3) + b1n[t];
    }
    __syncthreads();

    // Classifier: 16 warps over HRPB*NCLS=82 (row,class) pairs; shfl reduce
    const int warp = tid >> 5;
    const int lane = tid & 31;
    for (int pc = warp; pc < HRPB * NCLS; pc += 16) {
        const int rr = pc / NCLS;
        const int cc = pc % NCLS;
        float s = 0.f;
#pragma unroll
        for (int k = lane; k < 2 * D1; k += 32)
            s = fmaf(sH1[rr * 2 * D1 + k], Wfc[k * NCLS + cc], s);
#pragma unroll
        for (int off = 16; off > 0; off >>= 1)
            s += __shfl_xor_sync(0xFFFFFFFFu, s, off);
        if (lane == 0) out[(row0 + rr) * NCLS + cc] = s + bfc[cc];
    }
}

// ---------------------------------------------------------------------------
extern "C" void kernel_launch(void* const* d_in, const int* in_sizes, int n_in,
                              void* d_out, int out_size) {
    const float* features = (const float*)d_in[0];
    const int*   ids0     = (const int*)  d_in[1];
    const int*   ids1     = (const int*)  d_in[2];
    const int*   ids2     = (const int*)  d_in[3];
    const float* W2s      = (const float*)d_in[4];
    const float* b2s      = (const float*)d_in[5];
    const float* W2n      = (const float*)d_in[6];
    const float* b2n      = (const float*)d_in[7];
    const float* W1s      = (const float*)d_in[8];
    const float* b1s      = (const float*)d_in[9];
    const float* W1n      = (const float*)d_in[10];
    const float* b1n      = (const float*)d_in[11];
    const float* Wfc      = (const float*)d_in[12];
    const float* bfc      = (const float*)d_in[13];
    float* out = (float*)d_out;

    agg2_kernel<<<ROWS1, 128>>>(features, ids2);
    gemm2_kernel<<<dim3(ROWS1 / BM, 4), 256>>>(features, ids1, W2s, W2n);
    agg1_kernel<<<BATCH, 256>>>(b2s, b2n);
    head_kernel<<<BATCH / HRPB, 512>>>(features, ids0, W1s, b1s, W1n, b1n,
                                       Wfc, bfc, out);
}